// round 17
// baseline (speedup 1.0000x reference)
#include <cuda_runtime.h>
#include <cuda_fp16.h>
#include <cstdint>

// ---------------- problem constants -----------------------------------------
#define MROWS 8192      // B*C = 32*256
#define VIN   6890
#define VOUT  1723
#define KPAD  6912      // 108 * 64
#define NPAD  1792      // 14 * 128

// fp16 scratch + small split-tail partial buffer
__device__ __align__(16) __half g_Xh[(size_t)MROWS * KPAD];  // ~113 MB
__device__ __align__(16) __half g_Mh[(size_t)NPAD  * KPAD];  // ~25 MB
__device__ __align__(16) float  g_P[32 * 128 * 128];         // 2 MB (8 tiles x 4 quarters)

// ---------------- fused fp32 -> fp16 conversion (X and M in one launch) -----
__global__ void convert_all_v(const float* __restrict__ x,
                              const float* __restrict__ m) {
    int k8 = blockIdx.x * blockDim.x + threadIdx.x;
    if (k8 >= KPAD / 8) return;
    int row = blockIdx.y;
    int k = k8 * 8;
    __align__(16) __half h[8];

    const float* src;
    __half* dst;
    bool valid_row;
    if (row < MROWS) {
        src = x + (size_t)row * VIN + k;
        dst = &g_Xh[(size_t)row * KPAD + k];
        valid_row = true;
    } else {
        int mrow = row - MROWS;
        src = m + (size_t)mrow * VIN + k;
        dst = &g_Mh[(size_t)mrow * KPAD + k];
        valid_row = (mrow < VOUT);
    }

    if (valid_row) {
        if (k + 8 <= VIN) {
            #pragma unroll
            for (int j = 0; j < 4; ++j) {
                float2 f = *reinterpret_cast<const float2*>(src + 2 * j);
                h[2 * j]     = __float2half(f.x);
                h[2 * j + 1] = __float2half(f.y);
            }
        } else {
            #pragma unroll
            for (int j = 0; j < 8; ++j)
                h[j] = (k + j < VIN) ? __float2half(src[j]) : __float2half(0.0f);
        }
    } else {
        #pragma unroll
        for (int j = 0; j < 8; ++j) h[j] = __float2half(0.0f);
    }
    *reinterpret_cast<uint4*>(dst) = *reinterpret_cast<const uint4*>(h);
}

// ---------------- PTX helpers -----------------------------------------------
__device__ __forceinline__ void cp_async16(void* smem, const void* gmem) {
    uint32_t s = (uint32_t)__cvta_generic_to_shared(smem);
    asm volatile("cp.async.cg.shared.global [%0], [%1], 16;\n" :: "r"(s), "l"(gmem));
}
__device__ __forceinline__ void cp_commit() {
    asm volatile("cp.async.commit_group;\n" ::: "memory");
}
template<int N> __device__ __forceinline__ void cp_wait() {
    asm volatile("cp.async.wait_group %0;\n" :: "n"(N) : "memory");
}
__device__ __forceinline__ void ldsm_x4(uint32_t& r0, uint32_t& r1, uint32_t& r2,
                                        uint32_t& r3, const void* p) {
    uint32_t s = (uint32_t)__cvta_generic_to_shared(p);
    asm volatile("ldmatrix.sync.aligned.m8n8.x4.shared.b16 {%0,%1,%2,%3}, [%4];\n"
                 : "=r"(r0), "=r"(r1), "=r"(r2), "=r"(r3) : "r"(s));
}
__device__ __forceinline__ void mma16816(float* c, const uint32_t* a, const uint32_t* b) {
    asm volatile("mma.sync.aligned.m16n8k16.row.col.f32.f16.f16.f32 "
                 "{%0,%1,%2,%3}, {%4,%5,%6,%7}, {%8,%9}, {%0,%1,%2,%3};\n"
                 : "+f"(c[0]), "+f"(c[1]), "+f"(c[2]), "+f"(c[3])
                 : "r"(a[0]), "r"(a[1]), "r"(a[2]), "r"(a[3]),
                   "r"(b[0]), "r"(b[1]));
}

// ---------------- GEMM: C[8192,1723] = Xh * Mh^T -----------------------------
// R16 core (CTA 128x128, 4 warps 64x64, 3-stage, occ 2, drained kt-head).
// Tile schedule: 888 full-K tiles (exactly 6 per SM) + the last 8 tiles split
// into 4 K-quarters each (32 short CTAs, last bids -> fill the tail wave).
#define BM 128
#define BN 128
#define KC 64
#define STAGES 3
#define NSTG (KPAD / KC)        // 108
#define QSTG (NSTG / 4)         // 27
#define LDS_K 72                // 64 + 8 pad halves: LDSM conflict-free
#define A_HALVES (BM * LDS_K)   // 9216
#define B_HALVES (BN * LDS_K)   // 9216
#define STG_HALVES (A_HALVES + B_HALVES)       // 18432
#define SMEM_BYTES (STAGES * STG_HALVES * 2)   // 110,592 B per CTA
#define FULL_TILES 888
#define GRID_CTAS (FULL_TILES + 32)            // 920

__global__ __launch_bounds__(128, 2) void gemm_kernel(float* __restrict__ out) {
    extern __shared__ __align__(16) __half sm[];

    const int tid  = threadIdx.x;
    const int lane = tid & 31;
    const int warp = tid >> 5;    // 0..3
    const int wm   = warp & 1;    // m offset wm*64
    const int wn   = warp >> 1;   // n offset wn*64

    // tile decode: bids [0,888) = full-K tiles t=bid; bids [888,920) =
    // quarter CTAs of tiles 888..895 (m=63, n=6..13), 4 quarters each.
    const int bid = blockIdx.x;
    int t, split, h;
    if (bid < FULL_TILES) { t = bid; split = -1; h = 0; }
    else { h = bid - FULL_TILES; t = FULL_TILES + (h >> 2); split = h & 3; }
    const int mt = t / 14, nt = t % 14;   // n fastest -> A row-block stays hot
    const int bm = mt * BM,  bn = nt * BN;
    const int k0   = (split < 0) ? 0 : split * QSTG;
    const int nstg = (split < 0) ? NSTG : QSTG;

    const __half* Ag = g_Xh + (size_t)bm * KPAD + (size_t)k0 * KC;
    const __half* Bg = g_Mh + (size_t)bn * KPAD + (size_t)k0 * KC;

    // full-stage fill (prologue only)
    auto loadStage = [&](int s) {
        __half* aS = sm + (s % STAGES) * STG_HALVES;
        __half* bS = aS + A_HALVES;
        const int kb = s * KC;
        #pragma unroll
        for (int i = 0; i < 8; ++i) {
            const int c = tid + i * 128;
            const int r = c >> 3, k16 = c & 7;
            cp_async16(aS + r * LDS_K + k16 * 8,
                       Ag + (size_t)r * KPAD + kb + k16 * 8);
        }
        #pragma unroll
        for (int i = 0; i < 8; ++i) {
            const int c = tid + i * 128;
            const int r = c >> 3, k16 = c & 7;
            cp_async16(bS + r * LDS_K + k16 * 8,
                       Bg + (size_t)r * KPAD + kb + k16 * 8);
        }
    };

    // quarter-stage fill (q = 0..3), hidden under MMA blocks
    auto loadQuarter = [&](int s, int q) {
        __half* aS = sm + (s % STAGES) * STG_HALVES;
        __half* bS = aS + A_HALVES;
        const int kb = s * KC;
        #pragma unroll
        for (int i = 2 * q; i < 2 * q + 2; ++i) {
            const int c = tid + i * 128;
            const int r = c >> 3, k16 = c & 7;
            cp_async16(aS + r * LDS_K + k16 * 8,
                       Ag + (size_t)r * KPAD + kb + k16 * 8);
        }
        #pragma unroll
        for (int i = 2 * q; i < 2 * q + 2; ++i) {
            const int c = tid + i * 128;
            const int r = c >> 3, k16 = c & 7;
            cp_async16(bS + r * LDS_K + k16 * 8,
                       Bg + (size_t)r * KPAD + kb + k16 * 8);
        }
    };

    // double-buffered fragments (ks-level software pipeline)
    uint32_t afr[2][4][4];
    uint32_t bfr[2][8][2];

    const int a_row    = wm * 64 + (lane & 15);
    const int a_colsel = (lane >> 4) * 8;
    const int b_row    = wn * 64 + (lane & 7) + ((lane >> 4) << 3);
    const int b_colsel = ((lane >> 3) & 1) << 3;

    auto loadFrags = [&](const __half* aS, const __half* bS, int ks, int buf) {
        const int kstep = ks * 16;
        #pragma unroll
        for (int i = 0; i < 4; ++i)
            ldsm_x4(afr[buf][i][0], afr[buf][i][1], afr[buf][i][2], afr[buf][i][3],
                    aS + (a_row + i * 16) * LDS_K + kstep + a_colsel);
        #pragma unroll
        for (int j = 0; j < 4; ++j) {
            uint32_t t0, t1, t2, t3;
            ldsm_x4(t0, t1, t2, t3,
                    bS + (b_row + j * 16) * LDS_K + kstep + b_colsel);
            bfr[buf][2 * j][0] = t0;     bfr[buf][2 * j][1] = t1;
            bfr[buf][2 * j + 1][0] = t2; bfr[buf][2 * j + 1][1] = t3;
        }
    };

    float acc[4][8][4];
    #pragma unroll
    for (int i = 0; i < 4; ++i)
        #pragma unroll
        for (int j = 0; j < 8; ++j)
            #pragma unroll
            for (int e = 0; e < 4; ++e) acc[i][j][e] = 0.0f;

    loadStage(0); cp_commit();
    loadStage(1); cp_commit();
    cp_wait<1>();
    __syncthreads();               // stage 0 resident

    for (int kt = 0; kt < nstg; ++kt) {
        const bool doL = (kt + 2 < nstg);
        const __half* aS = sm + (kt % STAGES) * STG_HALVES;
        const __half* bS = aS + A_HALVES;

        loadFrags(aS, bS, 0, 0);   // first op after the barrier

        #pragma unroll
        for (int ks = 0; ks < 4; ++ks) {
            const int cur = ks & 1;
            if (ks < 3) loadFrags(aS, bS, ks + 1, cur ^ 1);
            if (doL) loadQuarter(kt + 2, ks);
            #pragma unroll
            for (int i = 0; i < 4; ++i)
                #pragma unroll
                for (int jn = 0; jn < 8; ++jn)
                    mma16816(acc[i][jn], afr[cur][i], bfr[cur][jn]);
        }

        cp_commit();
        cp_wait<1>();
        __syncthreads();           // stage kt+1 resident; all warps done with kt
    }

    const int g  = lane >> 2;
    const int tc = lane & 3;
    if (split < 0) {
        // full tile: scalar fp32 guarded stores (VOUT=1723 odd)
        #pragma unroll
        for (int i = 0; i < 4; ++i) {
            #pragma unroll
            for (int jn = 0; jn < 8; ++jn) {
                const int row = bm + wm * 64 + i * 16 + g;
                const int col = bn + wn * 64 + jn * 8 + tc * 2;
                if (col < VOUT)     out[(size_t)row * VOUT + col]           = acc[i][jn][0];
                if (col + 1 < VOUT) out[(size_t)row * VOUT + col + 1]       = acc[i][jn][1];
                if (col < VOUT)     out[(size_t)(row + 8) * VOUT + col]     = acc[i][jn][2];
                if (col + 1 < VOUT) out[(size_t)(row + 8) * VOUT + col + 1] = acc[i][jn][3];
            }
        }
    } else {
        // quarter CTA: unguarded float2 stores into private partial buffer
        float* P = g_P + (size_t)h * (128 * 128);
        #pragma unroll
        for (int i = 0; i < 4; ++i) {
            #pragma unroll
            for (int jn = 0; jn < 8; ++jn) {
                const int rl = wm * 64 + i * 16 + g;
                const int cl = wn * 64 + jn * 8 + tc * 2;
                *reinterpret_cast<float2*>(&P[rl * 128 + cl]) =
                    make_float2(acc[i][jn][0], acc[i][jn][1]);
                *reinterpret_cast<float2*>(&P[(rl + 8) * 128 + cl]) =
                    make_float2(acc[i][jn][2], acc[i][jn][3]);
            }
        }
    }
}

// ---------------- tail reduce: 8 tiles x 4 quarters -> out -------------------
__global__ void reduce_tail(float* __restrict__ out) {
    const int i = blockIdx.x * blockDim.x + threadIdx.x;
    if (i >= 8 * 128 * 128) return;
    const int tile = i >> 14;           // 0..7
    const int r = (i >> 7) & 127;
    const int c = i & 127;
    const int base = tile * 4;          // h = tile*4 + split
    float v = g_P[(size_t)(base + 0) * 16384 + r * 128 + c]
            + g_P[(size_t)(base + 1) * 16384 + r * 128 + c]
            + g_P[(size_t)(base + 2) * 16384 + r * 128 + c]
            + g_P[(size_t)(base + 3) * 16384 + r * 128 + c];
    const int row = 63 * 128 + r;       // split tiles: m=63, n=6..13
    const int col = (6 + tile) * 128 + c;
    if (col < VOUT) out[(size_t)row * VOUT + col] = v;
}

// ---------------- entry ------------------------------------------------------
extern "C" void kernel_launch(void* const* d_in, const int* in_sizes, int n_in,
                              void* d_out, int out_size) {
    const float* x = (const float*)d_in[0];  // (32,256,6890) fp32
    const float* M = (const float*)d_in[1];  // (1723,6890) fp32
    float* out = (float*)d_out;              // (32,256,1723) fp32

    cudaFuncSetAttribute(gemm_kernel, cudaFuncAttributeMaxDynamicSharedMemorySize,
                         SMEM_BYTES);

    convert_all_v<<<dim3((KPAD / 8 + 127) / 128, MROWS + NPAD), 128>>>(x, M);
    gemm_kernel<<<GRID_CTAS, 128, SMEM_BYTES>>>(out);
    reduce_tail<<<(8 * 128 * 128 + 255) / 256, 256>>>(out);
}